// round 3
// baseline (speedup 1.0000x reference)
#include <cuda_runtime.h>
#include <cuda_fp16.h>
#include <cstdint>

// B=4, C=128, N=32*64*64=131072, E=128, H=4, hd=32, GN groups=8 (16 ch/grp).
#define NTOT 131072
#define SCALE_ATTN 0.17677669529663687f   // 32^-0.5
#define EPSF 1e-5f

// ---------------- device scratch (static; no allocation) ----------------
__device__ float  d_apre[2048];            // [b][c][h] = scale*wtil*gn_g
__device__ float  d_part[1024 * 16];       // [blk][g][{sum,sumsq}]
__device__ float  d_rs[32];                // [b][g] rsqrt(var+eps)
__device__ float  d_alpha[512];            // [b][c]
__device__ float  d_beta[512];             // [b][c]
__device__ __half d_glg[16777216];         // [(b*8+g)*4+h][n]  group-partial logits
__device__ float  d_blk_m[1024 * 4];       // per k_main block, per head
__device__ float  d_blk_l[1024 * 4];
__device__ float  d_blk_acc[1024 * 512];   // per k_main block: [c*4+h]
__device__ float  d_y[2048];               // [b][h][c]

// ---------------- warp helpers ----------------
__device__ __forceinline__ float warpSum(float v) {
#pragma unroll
    for (int o = 16; o; o >>= 1) v += __shfl_xor_sync(0xffffffffu, v, o);
    return v;
}
__device__ __forceinline__ float warpMax(float v) {
#pragma unroll
    for (int o = 16; o; o >>= 1) v = fmaxf(v, __shfl_xor_sync(0xffffffffu, v, o));
    return v;
}

// ============================================================================
// K0: LayerNorm(e) -> q -> apre[b][c][h] = scale * (q^T Wk)[c] * gn_g[c]
// 1 block, 128 threads.
// ============================================================================
__global__ void __launch_bounds__(128) k_prep(
    const float* __restrict__ e,   const float* __restrict__ lng,
    const float* __restrict__ lnb, const float* __restrict__ Wq,
    const float* __restrict__ bq,  const float* __restrict__ Wk,
    const float* __restrict__ gng)
{
    __shared__ float en[512];    // [b][e]
    __shared__ float qsh[512];   // [b][o]
    int t = threadIdx.x, w = t >> 5, lane = t & 31;

    // warp w normalizes batch w
    float v[4]; float s = 0.f, s2 = 0.f;
#pragma unroll
    for (int k = 0; k < 4; k++) {
        v[k] = e[w * 128 + lane + 32 * k];
        s += v[k]; s2 += v[k] * v[k];
    }
    s = warpSum(s); s2 = warpSum(s2);
    float mu  = s * (1.0f / 128.0f);
    float var = s2 * (1.0f / 128.0f) - mu * mu;
    float rs  = rsqrtf(var + EPSF);
#pragma unroll
    for (int k = 0; k < 4; k++) {
        int ee = lane + 32 * k;
        en[w * 128 + ee] = (v[k] - mu) * rs * lng[ee] + lnb[ee];
    }
    __syncthreads();

    // q[b][o], thread t -> o
    for (int b = 0; b < 4; b++) {
        float acc = bq[t];
#pragma unroll 4
        for (int ee = 0; ee < 128; ee++)
            acc = fmaf(en[b * 128 + ee], Wq[t * 128 + ee], acc);
        qsh[b * 128 + t] = acc;
    }
    __syncthreads();

    // apre, thread t -> c
    float gc = gng[t];
    for (int b = 0; b < 4; b++)
#pragma unroll
        for (int h = 0; h < 4; h++) {
            float acc = 0.f;
#pragma unroll 4
            for (int d = 0; d < 32; d++)
                acc = fmaf(qsh[b * 128 + h * 32 + d], Wk[(h * 32 + d) * 128 + t], acc);
            d_apre[(b * 128 + t) * 4 + h] = SCALE_ATTN * acc * gc;
        }
}

// ============================================================================
// K1: fused GN-stats partials + group-partial logits (fp16).
// grid = 1024 (b = bid>>8, chunk ci of 512 n), 256 threads, 2 n/thread.
// ============================================================================
__global__ void __launch_bounds__(256, 6) k_fused(const float* __restrict__ raw) {
    __shared__ float4 a_sh[128];         // [c] -> 4 heads
    __shared__ float  sred[8 * 16];      // [warp][g*2+{s,s2}]
    int bid = blockIdx.x;
    int b = bid >> 8, ci = bid & 255;
    int t = threadIdx.x, w = t >> 5, lane = t & 31;

    if (t < 128) a_sh[t] = ((const float4*)d_apre)[b * 128 + t];
    __syncthreads();

    const float* rb = raw + (size_t)b * 128 * NTOT + ci * 512 + 2 * t;
    int nbase = ci * 512 + 2 * t;

#pragma unroll 1
    for (int g = 0; g < 8; g++) {
        float s = 0.f, s2 = 0.f;
        float gl[4][2] = {{0.f,0.f},{0.f,0.f},{0.f,0.f},{0.f,0.f}};
#pragma unroll
        for (int cl = 0; cl < 16; cl++) {
            int c = g * 16 + cl;
            float2 v = *(const float2*)(rb + (size_t)c * NTOT);
            float4 a = a_sh[c];
            gl[0][0] = fmaf(a.x, v.x, gl[0][0]); gl[0][1] = fmaf(a.x, v.y, gl[0][1]);
            gl[1][0] = fmaf(a.y, v.x, gl[1][0]); gl[1][1] = fmaf(a.y, v.y, gl[1][1]);
            gl[2][0] = fmaf(a.z, v.x, gl[2][0]); gl[2][1] = fmaf(a.z, v.y, gl[2][1]);
            gl[3][0] = fmaf(a.w, v.x, gl[3][0]); gl[3][1] = fmaf(a.w, v.y, gl[3][1]);
            s += v.x + v.y;
            s2 = fmaf(v.x, v.x, s2); s2 = fmaf(v.y, v.y, s2);
        }
#pragma unroll
        for (int h = 0; h < 4; h++) {
            __half2 hv = __floats2half2_rn(gl[h][0], gl[h][1]);
            *(__half2*)(d_glg + (size_t)((b * 8 + g) * 4 + h) * NTOT + nbase) = hv;
        }
        s = warpSum(s); s2 = warpSum(s2);
        if (lane == 0) { sred[w * 16 + g * 2] = s; sred[w * 16 + g * 2 + 1] = s2; }
    }
    __syncthreads();
    if (t < 16) {
        float S = 0.f;
#pragma unroll
        for (int ww = 0; ww < 8; ww++) S += sred[ww * 16 + t];
        d_part[bid * 16 + t] = S;
    }
}

// ============================================================================
// K1b: reduce stats partials -> rs[b,g], alpha/beta. 1 block, 128 threads.
// ============================================================================
__global__ void __launch_bounds__(128) k_finalize(
    const float* __restrict__ gng, const float* __restrict__ gnb)
{
    __shared__ float ps[64];
    __shared__ float mus[32], rss[32];
    int t = threadIdx.x;
    if (t < 64) {   // t = bg*2 + sel
        int bg = t >> 1, sel = t & 1;
        int b = bg >> 3, g = bg & 7;
        float S = 0.f;
#pragma unroll 8
        for (int ci = 0; ci < 256; ci++)
            S += d_part[(b * 256 + ci) * 16 + g * 2 + sel];
        ps[t] = S;
    }
    __syncthreads();
    if (t < 32) {
        const float inv = 1.0f / 2097152.0f;   // 16 ch * 131072 n
        float mu  = ps[2 * t] * inv;
        float var = ps[2 * t + 1] * inv - mu * mu;
        float rs  = rsqrtf(var + EPSF);
        mus[t] = mu; rss[t] = rs;
        d_rs[t] = rs;
    }
    __syncthreads();
    int c = t, g = c >> 4;
    for (int b = 0; b < 4; b++) {
        float rs = rss[b * 8 + g], mu = mus[b * 8 + g];
        float al = rs * gng[c];
        d_alpha[b * 128 + c] = al;
        d_beta[b * 128 + c]  = gnb[c] - mu * al;
    }
}

// ============================================================================
// K2: logits from glg -> block softmax -> weighted raw accumulation.
// grid = 1024 (b, chunk of 512 n), 256 threads.
// ============================================================================
__global__ void __launch_bounds__(256, 6) k_main(const float* __restrict__ raw) {
    __shared__ __align__(16) float w_sh[4][512];   // [h][n in chunk]
    __shared__ float red[32];                       // [warp][h]
    __shared__ float rs_sh[8];

    int bid = blockIdx.x;
    int b = bid >> 8, ci = bid & 255;
    int t = threadIdx.x, w = t >> 5, lane = t & 31;

    if (t < 8) rs_sh[t] = d_rs[b * 8 + t];
    __syncthreads();

    int nbase = ci * 512;

    // ---- Pass A: logits (2 n per thread) ----
    float lg[4][2] = {{0.f,0.f},{0.f,0.f},{0.f,0.f},{0.f,0.f}};
    const __half* gbase = d_glg + nbase + 2 * t;
#pragma unroll
    for (int g = 0; g < 8; g++) {
        float rsg = rs_sh[g];
#pragma unroll
        for (int h = 0; h < 4; h++) {
            __half2 hv = *(const __half2*)(gbase + (size_t)((b * 8 + g) * 4 + h) * NTOT);
            float2 f = __half22float2(hv);
            lg[h][0] = fmaf(rsg, f.x, lg[h][0]);
            lg[h][1] = fmaf(rsg, f.y, lg[h][1]);
        }
    }

    // ---- block softmax ----
    float m[4];
#pragma unroll
    for (int h = 0; h < 4; h++) {
        float mt = fmaxf(lg[h][0], lg[h][1]);
        mt = warpMax(mt);
        if (lane == 0) red[w * 4 + h] = mt;
    }
    __syncthreads();
#pragma unroll
    for (int h = 0; h < 4; h++) {
        float mm = red[h];
#pragma unroll
        for (int ww = 1; ww < 8; ww++) mm = fmaxf(mm, red[ww * 4 + h]);
        m[h] = mm;
    }
    __syncthreads();   // before red reuse
#pragma unroll
    for (int h = 0; h < 4; h++) {
        float w0 = __expf(lg[h][0] - m[h]);
        float w1 = __expf(lg[h][1] - m[h]);
        w_sh[h][2 * t]     = w0;
        w_sh[h][2 * t + 1] = w1;
        float ssum = warpSum(w0 + w1);
        if (lane == 0) red[w * 4 + h] = ssum;
    }
    __syncthreads();
    if (t == 0) {
#pragma unroll
        for (int h = 0; h < 4; h++) {
            float L = 0.f;
#pragma unroll
            for (int ww = 0; ww < 8; ww++) L += red[ww * 4 + h];
            d_blk_m[bid * 4 + h] = m[h];
            d_blk_l[bid * 4 + h] = L;
        }
    }

    // ---- Pass B: warp-per-channel weighted accumulation ----
    const float* rb = raw + (size_t)b * 128 * NTOT + nbase;
#pragma unroll 1
    for (int c = w; c < 128; c += 8) {
        const float4* rp = (const float4*)(rb + (size_t)c * NTOT);
        float a0 = 0.f, a1 = 0.f, a2 = 0.f, a3 = 0.f;
#pragma unroll
        for (int k = 0; k < 4; k++) {
            float4 r = rp[k * 32 + lane];
            int n = k * 128 + lane * 4;
            float4 w0 = *(const float4*)&w_sh[0][n];
            float4 w1 = *(const float4*)&w_sh[1][n];
            float4 w2 = *(const float4*)&w_sh[2][n];
            float4 w3 = *(const float4*)&w_sh[3][n];
            a0 = fmaf(w0.x, r.x, a0); a0 = fmaf(w0.y, r.y, a0);
            a0 = fmaf(w0.z, r.z, a0); a0 = fmaf(w0.w, r.w, a0);
            a1 = fmaf(w1.x, r.x, a1); a1 = fmaf(w1.y, r.y, a1);
            a1 = fmaf(w1.z, r.z, a1); a1 = fmaf(w1.w, r.w, a1);
            a2 = fmaf(w2.x, r.x, a2); a2 = fmaf(w2.y, r.y, a2);
            a2 = fmaf(w2.z, r.z, a2); a2 = fmaf(w2.w, r.w, a2);
            a3 = fmaf(w3.x, r.x, a3); a3 = fmaf(w3.y, r.y, a3);
            a3 = fmaf(w3.z, r.z, a3); a3 = fmaf(w3.w, r.w, a3);
        }
        a0 = warpSum(a0); a1 = warpSum(a1);
        a2 = warpSum(a2); a3 = warpSum(a3);
        if (lane == 0)
            ((float4*)(d_blk_acc + (size_t)bid * 512))[c] = make_float4(a0, a1, a2, a3);
    }
}

// ============================================================================
// K3a: combine block softmax partials -> y[b][h][c]. grid 16, 128 threads.
// ============================================================================
__global__ void __launch_bounds__(128) k_combine() {
    __shared__ float sm[256], sl[256], sf[256];
    int bh = blockIdx.x, b = bh >> 2, h = bh & 3;
    int t = threadIdx.x;   // c
#pragma unroll
    for (int r = 0; r < 2; r++) {
        int i = t + 128 * r;
        sm[i] = d_blk_m[(b * 256 + i) * 4 + h];
        sl[i] = d_blk_l[(b * 256 + i) * 4 + h];
    }
    __syncthreads();
    float M = -3.0e38f;
#pragma unroll 8
    for (int i = 0; i < 256; i++) M = fmaxf(M, sm[i]);
#pragma unroll
    for (int r = 0; r < 2; r++) {
        int i = t + 128 * r;
        sf[i] = __expf(sm[i] - M);
    }
    __syncthreads();
    float L = 0.f;
#pragma unroll 8
    for (int i = 0; i < 256; i++) L = fmaf(sl[i], sf[i], L);

    float r0 = 0.f, r1 = 0.f, r2 = 0.f, r3 = 0.f;
#pragma unroll 2
    for (int ci = 0; ci < 256; ci += 4) {
        r0 = fmaf(d_blk_acc[(size_t)(b * 256 + ci    ) * 512 + t * 4 + h], sf[ci    ], r0);
        r1 = fmaf(d_blk_acc[(size_t)(b * 256 + ci + 1) * 512 + t * 4 + h], sf[ci + 1], r1);
        r2 = fmaf(d_blk_acc[(size_t)(b * 256 + ci + 2) * 512 + t * 4 + h], sf[ci + 2], r2);
        r3 = fmaf(d_blk_acc[(size_t)(b * 256 + ci + 3) * 512 + t * 4 + h], sf[ci + 3], r3);
    }
    float r = ((r0 + r1) + (r2 + r3)) / L;
    d_y[(b * 4 + h) * 128 + t] = d_alpha[b * 128 + t] * r + d_beta[b * 128 + t];
}

// ============================================================================
// K3b: out = Wo @ (Wv @ y + bv) + bo. 1 block, 128 threads.
// ============================================================================
__global__ void __launch_bounds__(128) k_out(
    const float* __restrict__ Wv, const float* __restrict__ bv,
    const float* __restrict__ Wo, const float* __restrict__ bo,
    float* __restrict__ out)
{
    __shared__ float o1[512];
    int t = threadIdx.x;
    int h = t >> 5;
    for (int b = 0; b < 4; b++) {
        float acc = bv[t];
#pragma unroll 4
        for (int c = 0; c < 128; c++)
            acc = fmaf(Wv[t * 128 + c], d_y[(b * 4 + h) * 128 + c], acc);
        o1[b * 128 + t] = acc;
    }
    __syncthreads();
    for (int b = 0; b < 4; b++) {
        float acc = bo[t];
#pragma unroll 4
        for (int c = 0; c < 128; c++)
            acc = fmaf(Wo[t * 128 + c], o1[b * 128 + c], acc);
        out[b * 128 + t] = acc;
    }
}

// ============================================================================
extern "C" void kernel_launch(void* const* d_in, const int* in_sizes, int n_in,
                              void* d_out, int out_size) {
    const float* raw = (const float*)d_in[0];   // diff_spatial
    const float* evo = (const float*)d_in[1];
    const float* lng = (const float*)d_in[2];
    const float* lnb = (const float*)d_in[3];
    const float* gng = (const float*)d_in[4];
    const float* gnb = (const float*)d_in[5];
    const float* Wq  = (const float*)d_in[6];
    const float* bq  = (const float*)d_in[7];
    const float* Wk  = (const float*)d_in[8];
    // d_in[9] = bk: cancels in softmax
    const float* Wv  = (const float*)d_in[10];
    const float* bv  = (const float*)d_in[11];
    const float* Wo  = (const float*)d_in[12];
    const float* bo  = (const float*)d_in[13];
    float* out = (float*)d_out;

    k_prep<<<1, 128>>>(evo, lng, lnb, Wq, bq, Wk, gng);
    k_fused<<<1024, 256>>>(raw);
    k_finalize<<<1, 128>>>(gng, gnb);
    k_main<<<1024, 256>>>(raw);
    k_combine<<<16, 128>>>();
    k_out<<<1, 128>>>(Wv, bv, Wo, bo, out);
}

// round 4
// speedup vs baseline: 1.0229x; 1.0229x over previous
#include <cuda_runtime.h>
#include <cstdint>

// B=4, C=128, N=32*64*64=131072, E=128, H=4, hd=32, GN groups=8 (16 ch/grp).
#define NTOT 131072
#define SCALE_ATTN 0.17677669529663687f   // 32^-0.5
#define EPSF 1e-5f

// k_main tiling: 128 n per block, 1024 chunks per batch, grid 4096.
#define TSTRIDE 129
#define A_OFF   (128 * TSTRIDE)      // 16512 floats
#define W_OFF   (A_OFF + 512)        // a_sh: 128 float4
#define LG_OFF  (W_OFF + 512)        // w_sh: 4*128
#define SMEM_FLOATS (LG_OFF + 1024)  // lgred: 2*128*4
#define SMEM_BYTES (SMEM_FLOATS * 4) // 74240 B -> 3 blocks/SM

// ---------------- device scratch (static; no allocation) ----------------
__device__ float d_apre[2048];            // [b][c][h] = scale*wtil*gn_g
__device__ float d_part[8192 * 2];        // per k_stats block (sum, sumsq)
__device__ float d_a[2048];               // [b][c][h] logit weights (incl rs)
__device__ float d_alpha[512];            // [b][c]
__device__ float d_beta[512];             // [b][c]
__device__ float d_blk_m[4096 * 4];
__device__ float d_blk_l[4096 * 4];
__device__ float d_blk_acc[4096 * 512];   // 8 MB
__device__ float d_y[2048];               // [b][h][c]

__device__ __forceinline__ float warpSum(float v) {
#pragma unroll
    for (int o = 16; o; o >>= 1) v += __shfl_xor_sync(0xffffffffu, v, o);
    return v;
}
__device__ __forceinline__ float warpMax(float v) {
#pragma unroll
    for (int o = 16; o; o >>= 1) v = fmaxf(v, __shfl_xor_sync(0xffffffffu, v, o));
    return v;
}

// ============================================================================
// K0: LayerNorm(e) -> q -> apre[b][c][h] = scale * (q^T Wk)[c] * gn_g[c]
// ============================================================================
__global__ void __launch_bounds__(128) k_prep(
    const float* __restrict__ e,   const float* __restrict__ lng,
    const float* __restrict__ lnb, const float* __restrict__ Wq,
    const float* __restrict__ bq,  const float* __restrict__ Wk,
    const float* __restrict__ gng)
{
    __shared__ float en[512];
    __shared__ float qsh[512];
    int t = threadIdx.x, w = t >> 5, lane = t & 31;

    float v[4]; float s = 0.f, s2 = 0.f;
#pragma unroll
    for (int k = 0; k < 4; k++) {
        v[k] = e[w * 128 + lane + 32 * k];
        s += v[k]; s2 += v[k] * v[k];
    }
    s = warpSum(s); s2 = warpSum(s2);
    float mu  = s * (1.0f / 128.0f);
    float var = s2 * (1.0f / 128.0f) - mu * mu;
    float rs  = rsqrtf(var + EPSF);
#pragma unroll
    for (int k = 0; k < 4; k++) {
        int ee = lane + 32 * k;
        en[w * 128 + ee] = (v[k] - mu) * rs * lng[ee] + lnb[ee];
    }
    __syncthreads();

    for (int b = 0; b < 4; b++) {
        float acc = bq[t];
#pragma unroll 4
        for (int ee = 0; ee < 128; ee++)
            acc = fmaf(en[b * 128 + ee], Wq[t * 128 + ee], acc);
        qsh[b * 128 + t] = acc;
    }
    __syncthreads();

    float gc = gng[t];
    for (int b = 0; b < 4; b++)
#pragma unroll
        for (int h = 0; h < 4; h++) {
            float acc = 0.f;
#pragma unroll 4
            for (int d = 0; d < 32; d++)
                acc = fmaf(qsh[b * 128 + h * 32 + d], Wk[(h * 32 + d) * 128 + t], acc);
            d_apre[(b * 128 + t) * 4 + h] = SCALE_ATTN * acc * gc;
        }
}

// ============================================================================
// K1: GN stats partials. 8192 blocks x 256 thr; 8 float4 per thread.
// Region (b,g) = 16 contiguous channels = 2M floats; 256 chunks of 8192 floats.
// ============================================================================
__global__ void __launch_bounds__(256) k_stats(const float* __restrict__ raw) {
    int bid = blockIdx.x;
    int t = threadIdx.x, w = t >> 5, lane = t & 31;
    const float4* p = (const float4*)raw + (size_t)(bid >> 8) * (2097152 / 4)
                    + (size_t)(bid & 255) * 2048 + t;
    float s = 0.f, s2 = 0.f;
#pragma unroll
    for (int i = 0; i < 8; i++) {
        float4 v = p[256 * i];
        s  += (v.x + v.y) + (v.z + v.w);
        s2 += (v.x * v.x + v.y * v.y) + (v.z * v.z + v.w * v.w);
    }
    s = warpSum(s); s2 = warpSum(s2);
    __shared__ float rs_[8], rs2_[8];
    if (lane == 0) { rs_[w] = s; rs2_[w] = s2; }
    __syncthreads();
    if (t == 0) {
        float S = 0.f, S2 = 0.f;
#pragma unroll
        for (int i = 0; i < 8; i++) { S += rs_[i]; S2 += rs2_[i]; }
        d_part[bid * 2] = S; d_part[bid * 2 + 1] = S2;
    }
}

// ============================================================================
// K1b: reduce partials -> rs; build d_a / alpha / beta. 1 block, 128 thr.
// ============================================================================
__global__ void __launch_bounds__(128) k_finalize(
    const float* __restrict__ gng, const float* __restrict__ gnb)
{
    __shared__ float ps[64], mus[32], rss[32];
    int t = threadIdx.x;
    if (t < 64) {   // t = bg*2 + sel
        int bg = t >> 1, sel = t & 1;
        float S = 0.f;
#pragma unroll 8
        for (int ch = 0; ch < 256; ch++)
            S += d_part[(bg * 256 + ch) * 2 + sel];
        ps[t] = S;
    }
    __syncthreads();
    if (t < 32) {
        const float inv = 1.0f / 2097152.0f;
        float mu  = ps[2 * t] * inv;
        float var = ps[2 * t + 1] * inv - mu * mu;
        mus[t] = mu; rss[t] = rsqrtf(var + EPSF);
    }
    __syncthreads();
    int c = t, g = c >> 4;
    for (int b = 0; b < 4; b++) {
        float rs = rss[b * 8 + g], mu = mus[b * 8 + g];
        float al = rs * gng[c];
        d_alpha[b * 128 + c] = al;
        d_beta[b * 128 + c]  = gnb[c] - mu * al;
#pragma unroll
        for (int h = 0; h < 4; h++)
            d_a[(b * 128 + c) * 4 + h] = d_apre[(b * 128 + c) * 4 + h] * rs;
    }
}

// ============================================================================
// K2: fused logits + softmax + weighted accumulation; raw read ONCE into smem.
// grid 4096 (b, chunk of 128 n), 256 threads, 74240 B dynamic smem, 3/SM.
// tile layout [n][c], stride 129 -> bank = (n + c) mod 32.
// ============================================================================
__global__ void __launch_bounds__(256, 3) k_main(const float* __restrict__ raw) {
    extern __shared__ float sm[];
    float*  tile  = sm;
    float4* a_sh  = (float4*)(sm + A_OFF);
    float*  w_sh  = sm + W_OFF;
    float*  lgred = sm + LG_OFF;

    int bid = blockIdx.x;
    int b = bid >> 10, ci = bid & 1023;
    int t = threadIdx.x, w = t >> 5, lane = t & 31;

    if (t < 128) a_sh[t] = ((const float4*)d_a)[b * 128 + t];

    // ---- copy gmem -> tile: warp per channel, lane-strided n ----
    const float* rb = raw + (size_t)b * 128 * NTOT + ci * 128;
#pragma unroll 4
    for (int i = 0; i < 16; i++) {
        int c = i * 8 + w;
        const float* rp = rb + (size_t)c * NTOT;
        float v0 = rp[lane];
        float v1 = rp[lane + 32];
        float v2 = rp[lane + 64];
        float v3 = rp[lane + 96];
        tile[lane * TSTRIDE + c]        = v0;
        tile[(lane + 32) * TSTRIDE + c] = v1;
        tile[(lane + 64) * TSTRIDE + c] = v2;
        tile[(lane + 96) * TSTRIDE + c] = v3;
    }
    __syncthreads();

    // ---- Pass A: logits. thread -> (n, c-half) ----
    {
        int n = t & 127, half = t >> 7;
        float l0 = 0.f, l1 = 0.f, l2 = 0.f, l3 = 0.f;
        const float*  trow = tile + n * TSTRIDE + half * 64;
        const float4* arow = a_sh + half * 64;
#pragma unroll 8
        for (int c = 0; c < 64; c++) {
            float  v = trow[c];
            float4 a = arow[c];
            l0 = fmaf(a.x, v, l0); l1 = fmaf(a.y, v, l1);
            l2 = fmaf(a.z, v, l2); l3 = fmaf(a.w, v, l3);
        }
        ((float4*)lgred)[half * 128 + n] = make_float4(l0, l1, l2, l3);
    }
    __syncthreads();

    // combine halves, stage per-head logits (registers first, sync, overwrite)
    float4 p4, q4;
    if (t < 128) {
        p4 = ((float4*)lgred)[t];
        q4 = ((float4*)lgred)[128 + t];
    }
    __syncthreads();
    if (t < 128) {
        lgred[t]       = p4.x + q4.x;
        lgred[128 + t] = p4.y + q4.y;
        lgred[256 + t] = p4.z + q4.z;
        lgred[384 + t] = p4.w + q4.w;
    }
    __syncthreads();

    // ---- softmax: warp h handles head h ----
    if (w < 4) {
        const float* lr = lgred + w * 128;
        float x0 = lr[lane], x1 = lr[lane + 32], x2 = lr[lane + 64], x3 = lr[lane + 96];
        float m = fmaxf(fmaxf(x0, x1), fmaxf(x2, x3));
        m = warpMax(m);
        float e0 = __expf(x0 - m), e1 = __expf(x1 - m);
        float e2 = __expf(x2 - m), e3 = __expf(x3 - m);
        w_sh[w * 128 + lane]      = e0;
        w_sh[w * 128 + lane + 32] = e1;
        w_sh[w * 128 + lane + 64] = e2;
        w_sh[w * 128 + lane + 96] = e3;
        float s = warpSum((e0 + e1) + (e2 + e3));
        if (lane == 0) { d_blk_m[bid * 4 + w] = m; d_blk_l[bid * 4 + w] = s; }
    }
    __syncthreads();

    // ---- Pass B: thread owns 8 spread channels (c = cg + 16j) x 8 n ----
    int cg = t & 15, ng = t >> 4;   // ng in 0..15
    float acc[8][4];
#pragma unroll
    for (int j = 0; j < 8; j++)
#pragma unroll
        for (int h = 0; h < 4; h++) acc[j][h] = 0.f;

#pragma unroll
    for (int k = 0; k < 8; k++) {
        int nn = ng + 16 * k;
        float w0 = w_sh[nn], w1 = w_sh[128 + nn];
        float w2 = w_sh[256 + nn], w3 = w_sh[384 + nn];
        const float* tr = tile + nn * TSTRIDE + cg;
#pragma unroll
        for (int j = 0; j < 8; j++) {
            float v = tr[16 * j];
            acc[j][0] = fmaf(w0, v, acc[j][0]);
            acc[j][1] = fmaf(w1, v, acc[j][1]);
            acc[j][2] = fmaf(w2, v, acc[j][2]);
            acc[j][3] = fmaf(w3, v, acc[j][3]);
        }
    }
    // fold ng-pairs within warp (lanes l, l^16 share cg)
#pragma unroll
    for (int j = 0; j < 8; j++)
#pragma unroll
        for (int h = 0; h < 4; h++)
            acc[j][h] += __shfl_xor_sync(0xffffffffu, acc[j][h], 16);

    __syncthreads();   // tile reads complete -> overlay scratch on tile
    if (lane < 16) {
        float* sc = tile + (w * 16 + lane) * 35;   // stride 35: conflict-free
#pragma unroll
        for (int j = 0; j < 8; j++)
#pragma unroll
            for (int h = 0; h < 4; h++) sc[j * 4 + h] = acc[j][h];
    }
    __syncthreads();
    // final cross-warp reduction; thread t writes pairs p = 2t, 2t+1
    float2 outv;
#pragma unroll
    for (int e = 0; e < 2; e++) {
        int pp = t * 2 + e;
        int c = pp >> 2, h = pp & 3;
        int cg2 = c & 15, j = c >> 4;
        float s = 0.f;
#pragma unroll
        for (int ww = 0; ww < 8; ww++)
            s += tile[(ww * 16 + cg2) * 35 + j * 4 + h];
        if (e == 0) outv.x = s; else outv.y = s;
    }
    ((float2*)(d_blk_acc + (size_t)bid * 512))[t] = outv;
}

// ============================================================================
// K3a: combine 1024 block partials per (b,h) -> y. grid 16, 256 threads.
// ============================================================================
__global__ void __launch_bounds__(256) k_combine() {
    __shared__ float sf[1024];
    __shared__ float red[8];
    __shared__ float Msh, Lsh;
    __shared__ float pr[256];
    int bh = blockIdx.x, b = bh >> 2, h = bh & 3;
    int t = threadIdx.x, w = t >> 5, lane = t & 31;

    float ml[4], ll[4];
#pragma unroll
    for (int i = 0; i < 4; i++) {
        int ci = t + 256 * i;
        ml[i] = d_blk_m[(b * 1024 + ci) * 4 + h];
        ll[i] = d_blk_l[(b * 1024 + ci) * 4 + h];
    }
    float m = fmaxf(fmaxf(ml[0], ml[1]), fmaxf(ml[2], ml[3]));
    m = warpMax(m);
    if (lane == 0) red[w] = m;
    __syncthreads();
    if (t == 0) {
        float M = red[0];
#pragma unroll
        for (int i = 1; i < 8; i++) M = fmaxf(M, red[i]);
        Msh = M;
    }
    __syncthreads();
    float M = Msh;
    float Lp = 0.f;
#pragma unroll
    for (int i = 0; i < 4; i++) {
        float f = __expf(ml[i] - M);
        sf[t + 256 * i] = f;
        Lp = fmaf(ll[i], f, Lp);
    }
    Lp = warpSum(Lp);
    __syncthreads();   // red reuse
    if (lane == 0) red[w] = Lp;
    __syncthreads();
    if (t == 0) {
        float L = 0.f;
#pragma unroll
        for (int i = 0; i < 8; i++) L += red[i];
        Lsh = L;
    }
    __syncthreads();

    int c = t & 127, half = t >> 7;
    float r = 0.f;
    const float* ap = d_blk_acc + (size_t)(b * 1024 + half * 512) * 512 + c * 4 + h;
#pragma unroll 4
    for (int ci = 0; ci < 512; ci++)
        r = fmaf(ap[(size_t)ci * 512], sf[half * 512 + ci], r);
    pr[t] = r;
    __syncthreads();
    if (t < 128) {
        float rt = (pr[t] + pr[128 + t]) / Lsh;
        d_y[(b * 4 + h) * 128 + t] = d_alpha[b * 128 + t] * rt + d_beta[b * 128 + t];
    }
}

// ============================================================================
// K3b: out = Wo @ (Wv @ y + bv) + bo. 1 block, 128 threads.
// ============================================================================
__global__ void __launch_bounds__(128) k_out(
    const float* __restrict__ Wv, const float* __restrict__ bv,
    const float* __restrict__ Wo, const float* __restrict__ bo,
    float* __restrict__ out)
{
    __shared__ float o1[512];
    int t = threadIdx.x;
    int h = t >> 5;
    for (int b = 0; b < 4; b++) {
        float acc = bv[t];
#pragma unroll 4
        for (int c = 0; c < 128; c++)
            acc = fmaf(Wv[t * 128 + c], d_y[(b * 4 + h) * 128 + c], acc);
        o1[b * 128 + t] = acc;
    }
    __syncthreads();
    for (int b = 0; b < 4; b++) {
        float acc = bo[t];
#pragma unroll 4
        for (int c = 0; c < 128; c++)
            acc = fmaf(Wo[t * 128 + c], o1[b * 128 + c], acc);
        out[b * 128 + t] = acc;
    }
}

// ============================================================================
extern "C" void kernel_launch(void* const* d_in, const int* in_sizes, int n_in,
                              void* d_out, int out_size) {
    const float* raw = (const float*)d_in[0];
    const float* evo = (const float*)d_in[1];
    const float* lng = (const float*)d_in[2];
    const float* lnb = (const float*)d_in[3];
    const float* gng = (const float*)d_in[4];
    const float* gnb = (const float*)d_in[5];
    const float* Wq  = (const float*)d_in[6];
    const float* bq  = (const float*)d_in[7];
    const float* Wk  = (const float*)d_in[8];
    // d_in[9] = bk: cancels in softmax
    const float* Wv  = (const float*)d_in[10];
    const float* bv  = (const float*)d_in[11];
    const float* Wo  = (const float*)d_in[12];
    const float* bo  = (const float*)d_in[13];
    float* out = (float*)d_out;

    static bool attr_set = false;
    if (!attr_set) {
        cudaFuncSetAttribute(k_main, cudaFuncAttributeMaxDynamicSharedMemorySize,
                             SMEM_BYTES);
        attr_set = true;
    }

    k_prep<<<1, 128>>>(evo, lng, lnb, Wq, bq, Wk, gng);
    k_stats<<<8192, 256>>>(raw);
    k_finalize<<<1, 128>>>(gng, gnb);
    k_main<<<4096, 256, SMEM_BYTES>>>(raw);
    k_combine<<<16, 256>>>();
    k_out<<<1, 128>>>(Wv, bv, Wo, bo, out);
}